// round 1
// baseline (speedup 1.0000x reference)
#include <cuda_runtime.h>
#include <math.h>

// ---------------- problem constants ----------------
#define NN  100000
#define HD  128
#define EE  1600000
#define FIN 256
#define KD  5

// ---------------- scratch (static __device__, no allocation) ----------------
__device__ float g_h   [(size_t)NN * HD];
__device__ float g_h2  [(size_t)NN * HD];
__device__ float g_agg [(size_t)NN * HD];
__device__ float g_feat[(size_t)NN * HD];
__device__ float g_y0  [(size_t)NN * HD];
__device__ float g_y1  [(size_t)NN * HD];

__device__ int g_src[EE];
__device__ int g_dstv[EE];
__device__ int g_csr_src[EE];
__device__ int g_counts[NN];
__device__ int g_incl[NN];
__device__ int g_offs[NN + 1];
__device__ int g_cursor[NN];
__device__ int g_bsum[256];
__device__ int g_flag64;

// ---------------- edge-index dtype detection ----------------
// If the buffer is int64 (little-endian, values < 2^31), every odd 32-bit word
// of the first 32 elements is zero. For int32 data those words are random edge
// indices; P(all 32 are zero) ~ (1e-5)^32 ~ 0.
__global__ void detect_layout_kernel(const unsigned* __restrict__ p) {
    unsigned any = 0;
#pragma unroll
    for (int i = 1; i < 64; i += 2) any |= p[i];
    g_flag64 = (any == 0) ? 1 : 0;
}

__global__ void extract_edges_kernel(const void* __restrict__ edge_index, int E) {
    int i = blockIdx.x * blockDim.x + threadIdx.x;
    if (i >= E) return;
    if (g_flag64) {
        const long long* p = (const long long*)edge_index;
        g_src[i]  = (int)p[i];
        g_dstv[i] = (int)p[(size_t)E + i];
    } else {
        const int* p = (const int*)edge_index;
        g_src[i]  = p[i];
        g_dstv[i] = p[E + i];
    }
}

// ---------------- CSR build (counting sort by dst) ----------------
__global__ void zero_counts_kernel(int n) {
    int i = blockIdx.x * blockDim.x + threadIdx.x;
    if (i < n) g_counts[i] = 0;
}

__global__ void histogram_kernel(int E) {
    int i = blockIdx.x * blockDim.x + threadIdx.x;
    if (i < E) atomicAdd(&g_counts[g_dstv[i]], 1);
}

// blockwise inclusive scan (1024 elems / block)
__global__ void scan1_kernel(int n) {
    __shared__ int s[1024];
    int i = blockIdx.x * 1024 + threadIdx.x;
    int v = (i < n) ? g_counts[i] : 0;
    s[threadIdx.x] = v;
    __syncthreads();
#pragma unroll
    for (int off = 1; off < 1024; off <<= 1) {
        int t = (threadIdx.x >= off) ? s[threadIdx.x - off] : 0;
        __syncthreads();
        s[threadIdx.x] += t;
        __syncthreads();
    }
    if (i < n) g_incl[i] = s[threadIdx.x];
    if (threadIdx.x == 1023) g_bsum[blockIdx.x] = s[1023];
}

__global__ void scan2_kernel(int nb) {
    if (threadIdx.x == 0 && blockIdx.x == 0) {
        int run = 0;
        for (int i = 0; i < nb; ++i) {
            int v = g_bsum[i];
            g_bsum[i] = run;
            run += v;
        }
    }
}

__global__ void scan3_kernel(int n, int E) {
    int i = blockIdx.x * blockDim.x + threadIdx.x;
    if (i >= n) return;
    int off = g_bsum[i >> 10] + g_incl[i] - g_counts[i];
    g_offs[i] = off;
    g_cursor[i] = off;
    if (i == n - 1) g_offs[n] = E;
}

__global__ void scatter_csr_kernel(int E) {
    int i = blockIdx.x * blockDim.x + threadIdx.x;
    if (i >= E) return;
    int d = g_dstv[i];
    int p = atomicAdd(&g_cursor[d], 1);
    g_csr_src[p] = g_src[i];
}

// ---------------- mean aggregation: one warp per node ----------------
__global__ void mean_agg_kernel(const float* __restrict__ h, float* __restrict__ agg, int n) {
    int warp = (blockIdx.x * blockDim.x + threadIdx.x) >> 5;
    int lane = threadIdx.x & 31;
    if (warp >= n) return;
    int s = g_offs[warp];
    int e = g_offs[warp + 1];
    float4 acc = make_float4(0.f, 0.f, 0.f, 0.f);
    for (int i = s; i < e; ++i) {
        int src = g_csr_src[i];
        float4 v = ((const float4*)(h + (size_t)src * HD))[lane];
        acc.x += v.x; acc.y += v.y; acc.z += v.z; acc.w += v.w;
    }
    float inv = 1.0f / (float)max(e - s, 1);
    acc.x *= inv; acc.y *= inv; acc.z *= inv; acc.w *= inv;
    ((float4*)(agg + (size_t)warp * HD))[lane] = acc;
}

// ---------------- tiled SGEMM: C[M,128] = act(A1@W1 + A2@W2 + b) ----------------
// A row-major [M,K], W row-major [K,128]. Two-source support for conv layers.
#define BM 128
#define BN 128
#define BK 32

__global__ void __launch_bounds__(256) gemm_kernel(
    const float* __restrict__ A1, const float* __restrict__ W1, int K1,
    const float* __restrict__ A2, const float* __restrict__ W2, int K2,
    const float* __restrict__ bias, float* __restrict__ C, int M, int do_relu)
{
    __shared__ float As[BK][BM + 4];
    __shared__ float Wt[BK][BN];

    int tid = threadIdx.x;
    int tx = tid & 15;       // col group 0..15
    int ty = tid >> 4;       // row group 0..15
    int row0 = blockIdx.x * BM;

    float acc[8][8];
#pragma unroll
    for (int i = 0; i < 8; ++i)
#pragma unroll
        for (int j = 0; j < 8; ++j) acc[i][j] = 0.f;

    for (int pass = 0; pass < 2; ++pass) {
        const float* A = pass ? A2 : A1;
        const float* W = pass ? W2 : W1;
        int K = pass ? K2 : K1;
        if (A == nullptr) continue;

        for (int k0 = 0; k0 < K; k0 += BK) {
            // load A tile (128 x 32) transposed into As[k][row]
#pragma unroll
            for (int i = 0; i < 4; ++i) {
                int s = tid + i * 256;
                int r = s >> 3;
                int cv = (s & 7) * 4;
                float4 v = make_float4(0.f, 0.f, 0.f, 0.f);
                int gr = row0 + r;
                if (gr < M) v = *(const float4*)(A + (size_t)gr * K + k0 + cv);
                As[cv + 0][r] = v.x;
                As[cv + 1][r] = v.y;
                As[cv + 2][r] = v.z;
                As[cv + 3][r] = v.w;
            }
            // load W tile (32 x 128)
#pragma unroll
            for (int i = 0; i < 4; ++i) {
                int s = tid + i * 256;
                int r = s >> 5;
                int cv = (s & 31) * 4;
                float4 v = *(const float4*)(W + (size_t)(k0 + r) * BN + cv);
                *(float4*)&Wt[r][cv] = v;
            }
            __syncthreads();

#pragma unroll
            for (int kk = 0; kk < BK; ++kk) {
                float a[8], b[8];
#pragma unroll
                for (int i = 0; i < 4; ++i) {
                    ((float4*)a)[0] = *(const float4*)&As[kk][ty * 8];
                    ((float4*)a)[1] = *(const float4*)&As[kk][ty * 8 + 4];
                    ((float4*)b)[0] = *(const float4*)&Wt[kk][tx * 8];
                    ((float4*)b)[1] = *(const float4*)&Wt[kk][tx * 8 + 4];
                    break;
                }
#pragma unroll
                for (int i = 0; i < 8; ++i)
#pragma unroll
                    for (int j = 0; j < 8; ++j)
                        acc[i][j] += a[i] * b[j];
            }
            __syncthreads();
        }
    }

    // epilogue
#pragma unroll
    for (int i = 0; i < 8; ++i) {
        int r = row0 + ty * 8 + i;
        if (r >= M) continue;
#pragma unroll
        for (int j = 0; j < 8; ++j) {
            int c = tx * 8 + j;
            float v = acc[i][j] + bias[c];
            if (do_relu) v = fmaxf(v, 0.f);
            C[(size_t)r * BN + c] = v;
        }
    }
}

// ---------------- dist layer0 : y = relu(e[M,5] @ W0[5,128] + b0) ----------------
#define D0_ROWS 16
__global__ void dist0_kernel(const float* __restrict__ e, const float* __restrict__ W0,
                             const float* __restrict__ b0, float* __restrict__ y, int M)
{
    __shared__ float ws[KD * HD];
    for (int i = threadIdx.x; i < KD * HD; i += blockDim.x) ws[i] = W0[i];
    __syncthreads();
    int c = threadIdx.x;            // 128 threads = 128 cols
    float bv = b0[c];
    int r0 = blockIdx.x * D0_ROWS;
    for (int rr = 0; rr < D0_ROWS; ++rr) {
        int r = r0 + rr;
        if (r >= M) return;
        float acc = bv;
#pragma unroll
        for (int k = 0; k < KD; ++k)
            acc += e[(size_t)r * KD + k] * ws[k * HD + c];
        y[(size_t)r * HD + c] = fmaxf(acc, 0.f);
    }
}

// ---------------- final: out = sigmoid([feat|dist] @ fW + fb) ----------------
__global__ void final_kernel(const float* __restrict__ feat, const float* __restrict__ dist,
                             const float* __restrict__ fW, const float* __restrict__ fb,
                             float* __restrict__ out, int M)
{
    __shared__ float w[2 * HD];
    if (threadIdx.x < 2 * HD) w[threadIdx.x] = fW[threadIdx.x];
    __syncthreads();
    int warp = (blockIdx.x * blockDim.x + threadIdx.x) >> 5;
    int lane = threadIdx.x & 31;
    if (warp >= M) return;
    float4 f = ((const float4*)(feat + (size_t)warp * HD))[lane];
    float4 d = ((const float4*)(dist + (size_t)warp * HD))[lane];
    float4 wf = ((const float4*)w)[lane];
    float4 wd = ((const float4*)w)[lane + 32];
    float sum = f.x * wf.x + f.y * wf.y + f.z * wf.z + f.w * wf.w
              + d.x * wd.x + d.y * wd.y + d.z * wd.z + d.w * wd.w;
#pragma unroll
    for (int off = 16; off > 0; off >>= 1)
        sum += __shfl_xor_sync(0xFFFFFFFF, sum, off);
    if (lane == 0) {
        float v = sum + fb[0];
        out[warp] = 1.0f / (1.0f + __expf(-v));
    }
}

// ---------------- launch ----------------
extern "C" void kernel_launch(void* const* d_in, const int* in_sizes, int n_in,
                              void* d_out, int out_size)
{
    const float* x          = (const float*)d_in[0];
    const void*  edge_index = d_in[1];
    const float* edge_attr  = (const float*)d_in[2];
    const float* pre_W      = (const float*)d_in[3];
    const float* pre_b      = (const float*)d_in[4];
    const float* c1_Ws      = (const float*)d_in[5];
    const float* c1_Wn      = (const float*)d_in[6];
    const float* c1_b       = (const float*)d_in[7];
    const float* c2_Ws      = (const float*)d_in[8];
    const float* c2_Wn      = (const float*)d_in[9];
    const float* c2_b       = (const float*)d_in[10];
    const float* np_W       = (const float*)d_in[11];
    const float* np_b       = (const float*)d_in[12];
    const float* d_W0       = (const float*)d_in[13];
    const float* d_b0       = (const float*)d_in[14];
    const float* d_W1       = (const float*)d_in[15];
    const float* d_b1       = (const float*)d_in[16];
    const float* d_W2       = (const float*)d_in[17];
    const float* d_b2       = (const float*)d_in[18];
    const float* d_W3       = (const float*)d_in[19];
    const float* d_b3       = (const float*)d_in[20];
    const float* final_W    = (const float*)d_in[21];
    const float* final_b    = (const float*)d_in[22];
    float* out = (float*)d_out;

    int M = NN;
    int E = in_sizes[1] / 2;
    if (E > EE) E = EE;

    float *hbuf, *h2buf, *aggbuf, *featbuf, *y0buf, *y1buf;
    cudaGetSymbolAddress((void**)&hbuf,    g_h);
    cudaGetSymbolAddress((void**)&h2buf,   g_h2);
    cudaGetSymbolAddress((void**)&aggbuf,  g_agg);
    cudaGetSymbolAddress((void**)&featbuf, g_feat);
    cudaGetSymbolAddress((void**)&y0buf,   g_y0);
    cudaGetSymbolAddress((void**)&y1buf,   g_y1);

    // --- CSR build ---
    detect_layout_kernel<<<1, 1>>>((const unsigned*)edge_index);
    extract_edges_kernel<<<(E + 255) / 256, 256>>>(edge_index, E);
    zero_counts_kernel<<<(M + 255) / 256, 256>>>(M);
    histogram_kernel<<<(E + 255) / 256, 256>>>(E);
    int nb = (M + 1023) / 1024;
    scan1_kernel<<<nb, 1024>>>(M);
    scan2_kernel<<<1, 32>>>(nb);
    scan3_kernel<<<(M + 255) / 256, 256>>>(M, E);
    scatter_csr_kernel<<<(E + 255) / 256, 256>>>(E);

    int gemm_grid = (M + BM - 1) / BM;

    // --- feat path ---
    // h = x @ pre_W + pre_b
    gemm_kernel<<<gemm_grid, 256>>>(x, pre_W, FIN, nullptr, nullptr, 0, pre_b, hbuf, M, 0);
    // agg = mean_agg(h)
    mean_agg_kernel<<<(M * 32 + 255) / 256, 256>>>(hbuf, aggbuf, M);
    // h2 = relu(h @ c1_Ws + agg @ c1_Wn + c1_b)
    gemm_kernel<<<gemm_grid, 256>>>(hbuf, c1_Ws, HD, aggbuf, c1_Wn, HD, c1_b, h2buf, M, 1);
    // agg = mean_agg(h2)
    mean_agg_kernel<<<(M * 32 + 255) / 256, 256>>>(h2buf, aggbuf, M);
    // h = relu(h2 @ c2_Ws + agg @ c2_Wn + c2_b)
    gemm_kernel<<<gemm_grid, 256>>>(h2buf, c2_Ws, HD, aggbuf, c2_Wn, HD, c2_b, hbuf, M, 1);
    // feat = h @ np_W + np_b
    gemm_kernel<<<gemm_grid, 256>>>(hbuf, np_W, HD, nullptr, nullptr, 0, np_b, featbuf, M, 0);

    // --- dist path ---
    dist0_kernel<<<(M + D0_ROWS - 1) / D0_ROWS, 128>>>(edge_attr, d_W0, d_b0, y0buf, M);
    gemm_kernel<<<gemm_grid, 256>>>(y0buf, d_W1, HD, nullptr, nullptr, 0, d_b1, y1buf, M, 1);
    gemm_kernel<<<gemm_grid, 256>>>(y1buf, d_W2, HD, nullptr, nullptr, 0, d_b2, y0buf, M, 1);
    gemm_kernel<<<gemm_grid, 256>>>(y0buf, d_W3, HD, nullptr, nullptr, 0, d_b3, y1buf, M, 0);

    // --- merge + final ---
    final_kernel<<<(M * 32 + 255) / 256, 256>>>(featbuf, y1buf, final_W, final_b, out, M);
}